// round 14
// baseline (speedup 1.0000x reference)
#include <cuda_runtime.h>
#include <cuda_bf16.h>
#include <cstdint>

#define BB 2
#define NQ 300
#define NT 300
#define QP 320
#define IH 256
#define IW 256
#define HW 65536
#define NP 12544
#define SPLITK 8
#define KSPLIT (NP/SPLITK)      // 1568
#define KSTAGE 32
#define NSTAGES (KSPLIT/KSTAGE) // 49

// ---------------- scratch ----------------
__device__ __nv_bfloat16 g_om[(size_t)BB*QP*NP];   // [b][q][i] permuted p-axis
__device__ __nv_bfloat16 g_s [(size_t)BB*QP*NP];
__device__ __nv_bfloat16 g_tm[(size_t)BB*QP*NP];
__device__ float2 g_ppts[(size_t)BB*NP];           // permuted point coords
__device__ int g_cnt0[BB];
__device__ float g_negP[2*BB*NQ];
__device__ float g_sP  [2*BB*NQ];
__device__ float g_tmsum[BB*NT];
__device__ float g_C1p[(size_t)SPLITK*BB*NQ*NT];
__device__ float g_C2p[(size_t)SPLITK*BB*NQ*NT];

static __device__ __forceinline__ uint32_t smem_u32(const void* p) {
    return (uint32_t)__cvta_generic_to_shared(p);
}
static __device__ __forceinline__ void cpasync16(uint32_t dst, const void* src) {
    asm volatile("cp.async.cg.shared.global [%0], [%1], 16;\n" :: "r"(dst), "l"(src));
}
static __device__ __forceinline__ void cp_commit() { asm volatile("cp.async.commit_group;\n"); }
template<int N> static __device__ __forceinline__ void cp_wait() {
    asm volatile("cp.async.wait_group %0;\n" :: "n"(N));
}
static __device__ __forceinline__ float warp_sum(float v) {
    #pragma unroll
    for (int o = 16; o > 0; o >>= 1) v += __shfl_xor_sync(0xffffffffu, v, o);
    return v;
}

// ---------- K0: permute point coords by mask-half (deterministic) ------------
__global__ __launch_bounds__(1024) void k_build(const float* __restrict__ pts) {
    __shared__ int warpCnt0[32], warpCnt1[32], warpOff0[32], warpOff1[32];
    __shared__ int sTot0, sTot1, sFront, sBack;
    int b = blockIdx.x;
    int tid = threadIdx.x, warp = tid >> 5, lane = tid & 31;
    uint32_t lt = (1u << lane) - 1u;
    if (tid == 0) { sFront = 0; sBack = 0; }
    __syncthreads();

    const float2* pp = ((const float2*)pts) + (size_t)b*NP;
    float2* dst = g_ppts + (size_t)b*NP;

    for (int c0 = 0; c0 < NP; c0 += 1024) {
        int p = c0 + tid;
        bool active = p < NP;
        float2 pc = {0.f, 0.f};
        bool half1 = false;
        if (active) {
            pc = pp[p];
            float y = pc.y * IH - 0.5f;
            half1 = ((int)floorf(y) >= 128);
        }
        uint32_t m0 = __ballot_sync(0xffffffffu, active && !half1);
        uint32_t m1 = __ballot_sync(0xffffffffu, active && half1);
        int pre0 = __popc(m0 & lt);
        int pre1 = __popc(m1 & lt);
        if (lane == 0) { warpCnt0[warp] = __popc(m0); warpCnt1[warp] = __popc(m1); }
        __syncthreads();
        if (warp == 0) {
            int v0 = warpCnt0[lane], v1 = warpCnt1[lane];
            int c0w = v0, c1w = v1;
            #pragma unroll
            for (int o = 1; o < 32; o <<= 1) {
                int t0 = __shfl_up_sync(0xffffffffu, v0, o);
                int t1 = __shfl_up_sync(0xffffffffu, v1, o);
                if (lane >= o) { v0 += t0; v1 += t1; }
            }
            warpOff0[lane] = v0 - c0w;
            warpOff1[lane] = v1 - c1w;
            if (lane == 31) { sTot0 = v0; sTot1 = v1; }
        }
        __syncthreads();
        if (active) {
            int idx;
            if (!half1) idx = sFront + warpOff0[warp] + pre0;
            else        idx = NP - 1 - (sBack + warpOff1[warp] + pre1);
            dst[idx] = pc;
        }
        __syncthreads();
        if (tid == 0) { sFront += sTot0; sBack += sTot1; }
        __syncthreads();
    }
    if (tid == 0) g_cnt0[b] = sFront;
}

// ---------- K1: MERGED sampler. z in {0,1}: pred half-z; z==2: tgt ----------
__global__ __launch_bounds__(1024, 2)
void k_sample(const float* __restrict__ pred, const float* __restrict__ tgt) {
    extern __shared__ char sraw[];
    int q = blockIdx.x, b = blockIdx.y, z = blockIdx.z;
    int tid = threadIdx.x, warp = tid >> 5, lane = tid & 31;

    if (z < 2) {
        // ---------------- pred half-mask sampler (identical math to R8) ------
        int h = z;
        __nv_bfloat16* smask = (__nv_bfloat16*)sraw;   // 129*256 bf16
        float* rbuf = (float*)(sraw + 129*IW*2);

        int rows = h ? 128 : 129;
        const float* src = pred + ((size_t)(b*NQ + q))*HW + (size_t)h*128*IW;
        const float4* s4 = (const float4*)src;
        int n4 = rows * IW / 4;
        #pragma unroll 4
        for (int i = tid; i < n4; i += 1024) {
            float4 v = s4[i];
            __nv_bfloat162 p0 = __floats2bfloat162_rn(v.x, v.y);
            __nv_bfloat162 p1 = __floats2bfloat162_rn(v.z, v.w);
            uint2 u; u.x = *(uint32_t*)&p0; u.y = *(uint32_t*)&p1;
            ((uint2*)smask)[i] = u;
        }
        __syncthreads();

        int cnt0 = g_cnt0[b];
        int start = h ? cnt0 : 0;
        int end   = h ? NP : cnt0;
        int hrow  = h * 128;
        const float2* pp = g_ppts + (size_t)b*NP;
        size_t obase = ((size_t)(b*QP + q))*NP;
        float accA = 0.f, accB = 0.f;

        for (int i = start + tid; i < end; i += 1024) {
            float2 pc = pp[i];
            float x = pc.x * IW - 0.5f, y = pc.y * IH - 0.5f;
            float x0f = floorf(x), y0f = floorf(y);
            float wx = x - x0f, wy = y - y0f;
            int ix0 = (int)x0f, iy0 = (int)y0f;
            float vx0 = (ix0 >= 0) ? 1.f : 0.f;
            float vx1 = (ix0 + 1 <= IW - 1) ? 1.f : 0.f;
            float vy0 = (iy0 >= 0) ? 1.f : 0.f;
            float vy1 = (iy0 + 1 <= IH - 1) ? 1.f : 0.f;
            int xc0 = max(ix0, 0), xc1 = min(ix0 + 1, IW - 1);
            int yl0 = max(iy0, 0) - hrow;
            int yl1 = min(iy0 + 1, IH - 1) - hrow;
            float w00 = (1.f-wy)*(1.f-wx)*vy0*vx0;
            float w01 = (1.f-wy)*wx*vy0*vx1;
            float w10 = wy*(1.f-wx)*vy1*vx0;
            float w11 = wy*wx*vy1*vx1;
            float v = w00*__bfloat162float(smask[yl0*IW + xc0])
                    + w01*__bfloat162float(smask[yl0*IW + xc1])
                    + w10*__bfloat162float(smask[yl1*IW + xc0])
                    + w11*__bfloat162float(smask[yl1*IW + xc1]);
            float e = __expf(-fabsf(v));
            float t = 1.f + e;
            float inv = __fdividef(1.f, t);
            float s = (v >= 0.f) ? inv : e * inv;
            float sp = fmaxf(v, 0.f) + __logf(t);
            accA += sp; accB += s;
            g_om[obase + i] = __float2bfloat16(v);
            g_s [obase + i] = __float2bfloat16(s);
        }

        accA = warp_sum(accA);
        accB = warp_sum(accB);
        if (lane == 0) { rbuf[warp] = accA; rbuf[32 + warp] = accB; }
        __syncthreads();
        if (warp == 0) {
            float a = rbuf[lane];
            float bsum = rbuf[32 + lane];
            a = warp_sum(a);
            bsum = warp_sum(bsum);
            if (lane == 0) {
                g_negP[h*BB*NQ + b*NQ + q] = a;
                g_sP  [h*BB*NQ + b*NQ + q] = bsum;
            }
        }
    } else {
        // ---------------- tgt bit-mask sampler (1024 threads) ----------------
        uint32_t* sbits = (uint32_t*)sraw;            // HW/32 = 2048 words
        float* rbuf = (float*)(sraw + HW/8 + 128);    // after 8KB bits

        const float* src = tgt + ((size_t)(b*NT + q))*HW;
        const float4* s4 = (const float4*)src;
        #pragma unroll 2
        for (int w = warp; w < HW/128; w += 32) {
            float4 v = s4[w*32 + lane];
            uint32_t nib = (v.x != 0.f ? 1u : 0u) | (v.y != 0.f ? 2u : 0u)
                         | (v.z != 0.f ? 4u : 0u) | (v.w != 0.f ? 8u : 0u);
            uint32_t word = nib << ((lane & 7)*4);
            word |= __shfl_xor_sync(0xffffffffu, word, 1);
            word |= __shfl_xor_sync(0xffffffffu, word, 2);
            word |= __shfl_xor_sync(0xffffffffu, word, 4);
            if ((lane & 7) == 0) sbits[w*4 + (lane >> 3)] = word;
        }
        __syncthreads();

        const float2* pp = g_ppts + (size_t)b*NP;
        size_t obase = ((size_t)(b*QP + q))*NP;
        float acc = 0.f;

        for (int i = tid; i < NP; i += 1024) {
            float2 pc = pp[i];
            float x = pc.x * IW - 0.5f, y = pc.y * IH - 0.5f;
            float x0f = floorf(x), y0f = floorf(y);
            float wx = x - x0f, wy = y - y0f;
            int ix0 = (int)x0f, iy0 = (int)y0f;
            float vx0 = (ix0 >= 0) ? 1.f : 0.f;
            float vx1 = (ix0 + 1 <= IW - 1) ? 1.f : 0.f;
            float vy0 = (iy0 >= 0) ? 1.f : 0.f;
            float vy1 = (iy0 + 1 <= IH - 1) ? 1.f : 0.f;
            int xc0 = max(ix0, 0), xc1 = min(ix0 + 1, IW - 1);
            int yc0 = max(iy0, 0), yc1 = min(iy0 + 1, IH - 1);
            int r0 = yc0 * IW, r1 = yc1 * IW;
            float b00 = (float)((sbits[(r0 + xc0) >> 5] >> (xc0 & 31)) & 1u);
            float b01 = (float)((sbits[(r0 + xc1) >> 5] >> (xc1 & 31)) & 1u);
            float b10 = (float)((sbits[(r1 + xc0) >> 5] >> (xc0 & 31)) & 1u);
            float b11 = (float)((sbits[(r1 + xc1) >> 5] >> (xc1 & 31)) & 1u);
            float w00 = (1.f-wy)*(1.f-wx)*vy0*vx0;
            float w01 = (1.f-wy)*wx*vy0*vx1;
            float w10 = wy*(1.f-wx)*vy1*vx0;
            float w11 = wy*wx*vy1*vx1;
            float v = w00*b00 + w01*b01 + w10*b10 + w11*b11;
            acc += v;
            g_tm[obase + i] = __float2bfloat16(v);
        }

        acc = warp_sum(acc);
        if (lane == 0) rbuf[warp] = acc;
        __syncthreads();
        if (warp == 0) {
            float a = rbuf[lane];
            a = warp_sum(a);
            if (lane == 0) g_tmsum[b*NT + q] = a;
        }
    }
}

// ---------------- K2: dual bf16 GEMM, split-K 8, 3-stage ring (R8 config) ----
__device__ __forceinline__ void ldsm4(uint32_t* r, uint32_t addr) {
    asm volatile("ldmatrix.sync.aligned.m8n8.x4.shared.b16 {%0,%1,%2,%3}, [%4];"
        : "=r"(r[0]), "=r"(r[1]), "=r"(r[2]), "=r"(r[3]) : "r"(addr));
}
__device__ __forceinline__ void mma16816(float* d, const uint32_t* a, uint32_t b0, uint32_t b1) {
    asm volatile("mma.sync.aligned.m16n8k16.row.col.f32.bf16.bf16.f32 "
        "{%0,%1,%2,%3}, {%4,%5,%6,%7}, {%8,%9}, {%0,%1,%2,%3};"
        : "+f"(d[0]), "+f"(d[1]), "+f"(d[2]), "+f"(d[3])
        : "r"(a[0]), "r"(a[1]), "r"(a[2]), "r"(a[3]), "r"(b0), "r"(b1));
}

#define TPAD 40
#define TILE (64*TPAD)

__global__ __launch_bounds__(128) void k_gemm() {
    __shared__ __nv_bfloat16 sbuf[3][3][TILE];
    int m0 = blockIdx.x * 64, n0 = blockIdx.y * 64;
    int b = blockIdx.z >> 3, sk = blockIdx.z & 7;
    int kbeg = sk * KSPLIT;
    int tid = threadIdx.x, warp = tid >> 5, lane = tid & 31;
    int wm = (warp & 1) * 32, wn = (warp >> 1) * 32;

    const __nv_bfloat16* gA1 = g_om + (size_t)b*QP*NP;
    const __nv_bfloat16* gA2 = g_s  + (size_t)b*QP*NP;
    const __nv_bfloat16* gB  = g_tm + (size_t)b*QP*NP;

    int lrow = tid >> 2, lcol = (tid & 3) * 8;

    auto load_stage = [&](int buf, int k0) {
        #pragma unroll
        for (int it = 0; it < 2; it++) {
            int row = lrow + it*32;
            uint32_t d1 = smem_u32(&sbuf[buf][0][row*TPAD + lcol]);
            uint32_t d2 = smem_u32(&sbuf[buf][1][row*TPAD + lcol]);
            uint32_t d3 = smem_u32(&sbuf[buf][2][row*TPAD + lcol]);
            cpasync16(d1, gA1 + (size_t)(m0 + row)*NP + k0 + lcol);
            cpasync16(d2, gA2 + (size_t)(m0 + row)*NP + k0 + lcol);
            cpasync16(d3, gB  + (size_t)(n0 + row)*NP + k0 + lcol);
        }
    };

    float d1[2][4][4], d2[2][4][4];
    #pragma unroll
    for (int mi = 0; mi < 2; mi++)
        #pragma unroll
        for (int nj = 0; nj < 4; nj++)
            #pragma unroll
            for (int e = 0; e < 4; e++) { d1[mi][nj][e] = 0.f; d2[mi][nj][e] = 0.f; }

    int a_r = lane & 15, a_c = ((lane >> 4) & 1) * 8;
    int b_r = (lane & 7) + (((lane & 16) ? 8 : 0)), b_c = ((lane & 8) ? 8 : 0);

    load_stage(0, kbeg);            cp_commit();
    load_stage(1, kbeg + KSTAGE);   cp_commit();

    for (int s = 0; s < NSTAGES; s++) {
        if (s + 1 < NSTAGES) cp_wait<1>(); else cp_wait<0>();
        __syncthreads();
        if (s + 2 < NSTAGES) {
            load_stage((s + 2) % 3, kbeg + (s + 2)*KSTAGE);
            cp_commit();
        }

        int cur = s % 3;
        const __nv_bfloat16* t1 = sbuf[cur][0];
        const __nv_bfloat16* t2 = sbuf[cur][1];
        const __nv_bfloat16* tB = sbuf[cur][2];
        #pragma unroll
        for (int kk = 0; kk < 2; kk++) {
            uint32_t ao[2][4], as_[2][4], bf[2][4];
            #pragma unroll
            for (int mi = 0; mi < 2; mi++) {
                uint32_t off = (uint32_t)((wm + mi*16 + a_r)*TPAD + kk*16 + a_c)*2;
                ldsm4(ao[mi],  smem_u32(t1) + off);
                ldsm4(as_[mi], smem_u32(t2) + off);
            }
            #pragma unroll
            for (int nb = 0; nb < 2; nb++) {
                uint32_t off = (uint32_t)((wn + nb*16 + b_r)*TPAD + kk*16 + b_c)*2;
                ldsm4(bf[nb], smem_u32(tB) + off);
            }
            #pragma unroll
            for (int mi = 0; mi < 2; mi++)
                #pragma unroll
                for (int nj = 0; nj < 4; nj++) {
                    uint32_t b0 = bf[nj >> 1][(nj & 1)*2], b1 = bf[nj >> 1][(nj & 1)*2 + 1];
                    mma16816(d1[mi][nj], ao[mi],  b0, b1);
                    mma16816(d2[mi][nj], as_[mi], b0, b1);
                }
        }
    }

    float* C1 = g_C1p + (size_t)(sk*BB + b)*NQ*NT;
    float* C2 = g_C2p + (size_t)(sk*BB + b)*NQ*NT;
    int r = lane >> 2, c2 = (lane & 3)*2;
    #pragma unroll
    for (int mi = 0; mi < 2; mi++)
        #pragma unroll
        for (int nj = 0; nj < 4; nj++) {
            int m = m0 + wm + mi*16 + r;
            int n = n0 + wn + nj*8 + c2;
            if (m < NQ) {
                if (n     < NT) { C1[(size_t)m*NT + n]     = d1[mi][nj][0]; C2[(size_t)m*NT + n]     = d2[mi][nj][0]; }
                if (n + 1 < NT) { C1[(size_t)m*NT + n + 1] = d1[mi][nj][1]; C2[(size_t)m*NT + n + 1] = d2[mi][nj][1]; }
            }
            if (m + 8 < NQ) {
                if (n     < NT) { C1[(size_t)(m+8)*NT + n]     = d1[mi][nj][2]; C2[(size_t)(m+8)*NT + n]     = d2[mi][nj][2]; }
                if (n + 1 < NT) { C1[(size_t)(m+8)*NT + n + 1] = d1[mi][nj][3]; C2[(size_t)(m+8)*NT + n + 1] = d2[mi][nj][3]; }
            }
        }
}

// ---------------- K3: final cost --------------------------------------------
__global__ void k_final(const float* __restrict__ pb, const float* __restrict__ tb,
                        float* __restrict__ out) {
    int idx = blockIdx.x * 256 + threadIdx.x;
    if (idx >= BB*NQ*NT) return;
    int t = idx % NT; int r = idx / NT; int q = r % NQ; int b = r / NQ;

    float c1 = 0.f, c2 = 0.f;
    #pragma unroll
    for (int sk = 0; sk < SPLITK; sk++) {
        size_t off = ((size_t)(sk*BB + b)*NQ + q)*NT + t;
        c1 += g_C1p[off]; c2 += g_C2p[off];
    }
    float neg = g_negP[b*NQ + q] + g_negP[BB*NQ + b*NQ + q];
    float ss  = g_sP  [b*NQ + q] + g_sP  [BB*NQ + b*NQ + q];
    float ts  = g_tmsum[b*NT + t];
    float cost_mask = (neg - c1) * (1.0f/(float)NP);
    float cost_dice = 1.f - (2.f*c2 + 1.f) / (ss + ts + 1.f);

    float4 pbox = ((const float4*)pb)[(size_t)b*NQ + q];
    float4 tbox = ((const float4*)tb)[(size_t)b*NT + t];
    float l1 = fabsf(pbox.x - tbox.x) + fabsf(pbox.y - tbox.y)
             + fabsf(pbox.z - tbox.z) + fabsf(pbox.w - tbox.w);

    float ax0 = pbox.x - 0.5f*pbox.z, ay0 = pbox.y - 0.5f*pbox.w;
    float ax1 = pbox.x + 0.5f*pbox.z, ay1 = pbox.y + 0.5f*pbox.w;
    float bx0 = tbox.x - 0.5f*tbox.z, by0 = tbox.y - 0.5f*tbox.w;
    float bx1 = tbox.x + 0.5f*tbox.z, by1 = tbox.y + 0.5f*tbox.w;
    float areaA = (ax1 - ax0)*(ay1 - ay0);
    float areaB = (bx1 - bx0)*(by1 - by0);
    float iw = fmaxf(fminf(ax1, bx1) - fmaxf(ax0, bx0), 0.f);
    float ih = fmaxf(fminf(ay1, by1) - fmaxf(ay0, by0), 0.f);
    float inter = iw * ih;
    float uni = areaA + areaB - inter;
    float iou = inter / uni;
    float ew = fmaxf(fmaxf(ax1, bx1) - fminf(ax0, bx0), 0.f);
    float eh = fmaxf(fmaxf(ay1, by1) - fminf(ay0, by0), 0.f);
    float areaE = ew * eh;
    float giou = iou - (areaE - uni) / areaE;

    out[idx] = 5.f*cost_mask + 5.f*cost_dice + 5.f*l1 - 2.f*giou;
}

// ---------------- launch ------------------------------------------------------
extern "C" void kernel_launch(void* const* d_in, const int* in_sizes, int n_in,
                              void* d_out, int out_size) {
    const float* pred_masks = (const float*)d_in[0];
    const float* tgt_masks  = (const float*)d_in[1];
    const float* pred_boxes = (const float*)d_in[2];
    const float* tgt_boxes  = (const float*)d_in[3];
    const float* pts        = (const float*)d_in[4];
    float* out = (float*)d_out;

    static bool attr_done = []() {
        cudaFuncSetAttribute(k_sample, cudaFuncAttributeMaxDynamicSharedMemorySize,
                             129*IW*2 + 64*4);
        return true;
    }();
    (void)attr_done;

    const int smem_sample = 129*IW*2 + 64*4;   // 66304 B (pred layout; tgt uses prefix)

    k_build<<<BB, 1024>>>(pts);
    k_sample<<<dim3(NQ, BB, 3), 1024, smem_sample>>>(pred_masks, tgt_masks);
    k_gemm<<<dim3(5, 5, BB*SPLITK), 128>>>();
    k_final<<<(BB*NQ*NT + 255)/256, 256>>>(pred_boxes, tgt_boxes, out);
}

// round 15
// speedup vs baseline: 1.0526x; 1.0526x over previous
#include <cuda_runtime.h>
#include <cuda_bf16.h>
#include <cstdint>

#define BB 2
#define NQ 300
#define NT 300
#define QP 320
#define IH 256
#define IW 256
#define HW 65536
#define NP 12544
#define SPLITK 8
#define KSPLIT (NP/SPLITK)      // 1568
#define KSTAGE 32
#define NSTAGES (KSPLIT/KSTAGE) // 49

#define PSTRIDE 264             // pred smem row stride (elems), interior at col 4
#define PROWS 130
#define PRED_MASK_BYTES (PROWS*PSTRIDE*2)   // 68640

// ---------------- scratch ----------------
__device__ __nv_bfloat16 g_om[(size_t)BB*QP*NP];   // [b][q][i] permuted p-axis
__device__ __nv_bfloat16 g_s [(size_t)BB*QP*NP];
__device__ __nv_bfloat16 g_tm[(size_t)BB*QP*NP];
__device__ float2 g_ppts[(size_t)BB*NP];           // permuted point coords
__device__ int g_cnt0[BB];
__device__ float g_negP[2*BB*NQ];
__device__ float g_sP  [2*BB*NQ];
__device__ float g_tmsum[BB*NT];
__device__ float g_C1p[(size_t)SPLITK*BB*NQ*NT];
__device__ float g_C2p[(size_t)SPLITK*BB*NQ*NT];

static __device__ __forceinline__ uint32_t smem_u32(const void* p) {
    return (uint32_t)__cvta_generic_to_shared(p);
}
static __device__ __forceinline__ void cpasync16(uint32_t dst, const void* src) {
    asm volatile("cp.async.cg.shared.global [%0], [%1], 16;\n" :: "r"(dst), "l"(src));
}
static __device__ __forceinline__ void cp_commit() { asm volatile("cp.async.commit_group;\n"); }
template<int N> static __device__ __forceinline__ void cp_wait() {
    asm volatile("cp.async.wait_group %0;\n" :: "n"(N));
}
static __device__ __forceinline__ float warp_sum(float v) {
    #pragma unroll
    for (int o = 16; o > 0; o >>= 1) v += __shfl_xor_sync(0xffffffffu, v, o);
    return v;
}

// ---------- K0: permute point coords by mask-half (deterministic) ------------
__global__ __launch_bounds__(1024) void k_build(const float* __restrict__ pts) {
    __shared__ int warpCnt0[32], warpCnt1[32], warpOff0[32], warpOff1[32];
    __shared__ int sTot0, sTot1, sFront, sBack;
    int b = blockIdx.x;
    int tid = threadIdx.x, warp = tid >> 5, lane = tid & 31;
    uint32_t lt = (1u << lane) - 1u;
    if (tid == 0) { sFront = 0; sBack = 0; }
    __syncthreads();

    const float2* pp = ((const float2*)pts) + (size_t)b*NP;
    float2* dst = g_ppts + (size_t)b*NP;

    for (int c0 = 0; c0 < NP; c0 += 1024) {
        int p = c0 + tid;
        bool active = p < NP;
        float2 pc = {0.f, 0.f};
        bool half1 = false;
        if (active) {
            pc = pp[p];
            float y = pc.y * IH - 0.5f;
            half1 = ((int)floorf(y) >= 128);
        }
        uint32_t m0 = __ballot_sync(0xffffffffu, active && !half1);
        uint32_t m1 = __ballot_sync(0xffffffffu, active && half1);
        int pre0 = __popc(m0 & lt);
        int pre1 = __popc(m1 & lt);
        if (lane == 0) { warpCnt0[warp] = __popc(m0); warpCnt1[warp] = __popc(m1); }
        __syncthreads();
        if (warp == 0) {
            int v0 = warpCnt0[lane], v1 = warpCnt1[lane];
            int c0w = v0, c1w = v1;
            #pragma unroll
            for (int o = 1; o < 32; o <<= 1) {
                int t0 = __shfl_up_sync(0xffffffffu, v0, o);
                int t1 = __shfl_up_sync(0xffffffffu, v1, o);
                if (lane >= o) { v0 += t0; v1 += t1; }
            }
            warpOff0[lane] = v0 - c0w;
            warpOff1[lane] = v1 - c1w;
            if (lane == 31) { sTot0 = v0; sTot1 = v1; }
        }
        __syncthreads();
        if (active) {
            int idx;
            if (!half1) idx = sFront + warpOff0[warp] + pre0;
            else        idx = NP - 1 - (sBack + warpOff1[warp] + pre1);
            dst[idx] = pc;
        }
        __syncthreads();
        if (tid == 0) { sFront += sTot0; sBack += sTot1; }
        __syncthreads();
    }
    if (tid == 0) g_cnt0[b] = sFront;
}

// ---------- K1a: pred sampler, zero-border smem tile, no boundary ALU --------
__global__ __launch_bounds__(1024, 2)
void k_sample_pred(const float* __restrict__ pred) {
    extern __shared__ char sraw[];
    __nv_bfloat16* smask = (__nv_bfloat16*)sraw;           // 130 x 264
    float* rbuf = (float*)(sraw + PRED_MASK_BYTES);        // 64 floats
    int q = blockIdx.x, b = blockIdx.y, h = blockIdx.z;
    int tid = threadIdx.x, warp = tid >> 5, lane = tid & 31;

    // zero borders: the zero row (h? row128 : row0) + cols 3 & 260 of all rows
    {
        int zr = h ? 128 : 0;
        for (int c = tid; c < PSTRIDE; c += 1024) smask[zr*PSTRIDE + c] = __float2bfloat16(0.f);
        if (tid < PROWS*2) {
            int rr = tid >> 1, cc = (tid & 1) ? 260 : 3;
            smask[rr*PSTRIDE + cc] = __float2bfloat16(0.f);
        }
    }

    // load interior rows: half0 -> mask rows 0..128 at smem rows 1..129
    //                     half1 -> mask rows 128..255 at smem rows 0..127
    int nrows = h ? 128 : 129;
    int mr0   = h ? 128 : 0;
    int sr0   = h ? 0 : 1;
    const float* src = pred + ((size_t)(b*NQ + q))*HW + (size_t)mr0*IW;
    int n4 = nrows * (IW/4);
    for (int i = tid; i < n4; i += 1024) {
        int r = i >> 6, c4 = i & 63;                 // 64 float4 per row
        float4 v = ((const float4*)src)[(size_t)r*64 + c4];
        __nv_bfloat162 p0 = __floats2bfloat162_rn(v.x, v.y);
        __nv_bfloat162 p1 = __floats2bfloat162_rn(v.z, v.w);
        uint2 u; u.x = *(uint32_t*)&p0; u.y = *(uint32_t*)&p1;
        *(uint2*)&smask[(sr0 + r)*PSTRIDE + 4 + c4*4] = u;
    }
    __syncthreads();

    int cnt0 = g_cnt0[b];
    int start = h ? cnt0 : 0;
    int end   = h ? NP : cnt0;
    int rowbase = h ? 128 : -1;                      // smem row = iy0 - rowbase
    const float2* pp = g_ppts + (size_t)b*NP;
    size_t obase = ((size_t)(b*QP + q))*NP;
    float accA = 0.f, accB = 0.f;

    for (int i = start + tid; i < end; i += 1024) {
        float2 pc = pp[i];
        float x = fmaf(pc.x, (float)IW, -0.5f);
        float y = fmaf(pc.y, (float)IH, -0.5f);
        float x0f = floorf(x), y0f = floorf(y);
        float wx = x - x0f, wy = y - y0f;
        int ix0 = (int)x0f, iy0 = (int)y0f;
        int a = (iy0 - rowbase)*PSTRIDE + ix0 + 4;
        float m00 = __bfloat162float(smask[a]);
        float m01 = __bfloat162float(smask[a + 1]);
        float m10 = __bfloat162float(smask[a + PSTRIDE]);
        float m11 = __bfloat162float(smask[a + PSTRIDE + 1]);
        float omx = 1.f - wx, omy = 1.f - wy;
        float v = omy*(omx*m00 + wx*m01) + wy*(omx*m10 + wx*m11);
        float e = __expf(-fabsf(v));
        float t = 1.f + e;
        float inv = __fdividef(1.f, t);
        float s = (v >= 0.f) ? inv : e * inv;
        float sp = fmaxf(v, 0.f) + __logf(t);
        accA += sp; accB += s;
        g_om[obase + i] = __float2bfloat16(v);
        g_s [obase + i] = __float2bfloat16(s);
    }

    accA = warp_sum(accA);
    accB = warp_sum(accB);
    if (lane == 0) { rbuf[warp] = accA; rbuf[32 + warp] = accB; }
    __syncthreads();
    if (warp == 0) {
        float a = rbuf[lane];
        float bsum = rbuf[32 + lane];
        a = warp_sum(a);
        bsum = warp_sum(bsum);
        if (lane == 0) {
            g_negP[h*BB*NQ + b*NQ + q] = a;
            g_sP  [h*BB*NQ + b*NQ + q] = bsum;
        }
    }
}

// ---------- K1b: tgt sampler, guarded bit-mask + funnel-shift extraction -----
// word layout: row r (mask rows -1..256) base = (r+1)*10 + 1; words base..base+7
// guard words at base-1 and base+8; guard rows -1 and 256 all zero.
__global__ __launch_bounds__(512, 4)
void k_sample_tgt(const float* __restrict__ tgt) {
    __shared__ uint32_t sbits[2580];
    __shared__ float rbuf[16];
    int q = blockIdx.x, b = blockIdx.y;
    int tid = threadIdx.x, warp = tid >> 5, lane = tid & 31;

    for (int i = tid; i < 2580; i += 512) sbits[i] = 0;
    __syncthreads();

    const float* src = tgt + ((size_t)(b*NT + q))*HW;
    const float4* s4 = (const float4*)src;
    // group g covers 128 px: row = g>>1, word-half = g&1 (4 words)
    #pragma unroll 4
    for (int g = warp; g < HW/128; g += 16) {
        float4 v = s4[g*32 + lane];
        uint32_t nib = (v.x != 0.f ? 1u : 0u) | (v.y != 0.f ? 2u : 0u)
                     | (v.z != 0.f ? 4u : 0u) | (v.w != 0.f ? 8u : 0u);
        uint32_t word = nib << ((lane & 7)*4);
        word |= __shfl_xor_sync(0xffffffffu, word, 1);
        word |= __shfl_xor_sync(0xffffffffu, word, 2);
        word |= __shfl_xor_sync(0xffffffffu, word, 4);
        if ((lane & 7) == 0) {
            int row = g >> 1;
            sbits[(row + 1)*10 + 1 + (g & 1)*4 + (lane >> 3)] = word;
        }
    }
    __syncthreads();

    const float2* pp = g_ppts + (size_t)b*NP;
    size_t obase = ((size_t)(b*QP + q))*NP;
    float acc = 0.f;

    for (int i = tid; i < NP; i += 512) {
        float2 pc = pp[i];
        float x = fmaf(pc.x, (float)IW, -0.5f);
        float y = fmaf(pc.y, (float)IH, -0.5f);
        float x0f = floorf(x), y0f = floorf(y);
        float wx = x - x0f, wy = y - y0f;
        int ix0 = (int)x0f, iy0 = (int)y0f;
        int wi = (iy0 + 1)*10 + 1 + (ix0 >> 5);      // arithmetic shift: -1 -> guard
        int bit = ix0 & 31;
        uint32_t p0 = __funnelshift_r(sbits[wi],      sbits[wi + 1],  bit) & 3u;
        uint32_t p1 = __funnelshift_r(sbits[wi + 10], sbits[wi + 11], bit) & 3u;
        float b00 = (float)(p0 & 1u), b01 = (float)(p0 >> 1);
        float b10 = (float)(p1 & 1u), b11 = (float)(p1 >> 1);
        float omx = 1.f - wx, omy = 1.f - wy;
        float v = omy*(omx*b00 + wx*b01) + wy*(omx*b10 + wx*b11);
        acc += v;
        g_tm[obase + i] = __float2bfloat16(v);
    }

    acc = warp_sum(acc);
    if (lane == 0) rbuf[warp] = acc;
    __syncthreads();
    if (warp == 0 && lane < 16) {
        float a = rbuf[lane];
        #pragma unroll
        for (int o = 8; o > 0; o >>= 1) a += __shfl_xor_sync(0xffffu, a, o);
        if (lane == 0) g_tmsum[b*NT + q] = a;
    }
}

// ---------------- K2: dual bf16 GEMM, split-K 8, 3-stage ring (R8 config) ----
__device__ __forceinline__ void ldsm4(uint32_t* r, uint32_t addr) {
    asm volatile("ldmatrix.sync.aligned.m8n8.x4.shared.b16 {%0,%1,%2,%3}, [%4];"
        : "=r"(r[0]), "=r"(r[1]), "=r"(r[2]), "=r"(r[3]) : "r"(addr));
}
__device__ __forceinline__ void mma16816(float* d, const uint32_t* a, uint32_t b0, uint32_t b1) {
    asm volatile("mma.sync.aligned.m16n8k16.row.col.f32.bf16.bf16.f32 "
        "{%0,%1,%2,%3}, {%4,%5,%6,%7}, {%8,%9}, {%0,%1,%2,%3};"
        : "+f"(d[0]), "+f"(d[1]), "+f"(d[2]), "+f"(d[3])
        : "r"(a[0]), "r"(a[1]), "r"(a[2]), "r"(a[3]), "r"(b0), "r"(b1));
}

#define TPAD 40
#define TILE (64*TPAD)

__global__ __launch_bounds__(128) void k_gemm() {
    __shared__ __nv_bfloat16 sbuf[3][3][TILE];
    int m0 = blockIdx.x * 64, n0 = blockIdx.y * 64;
    int b = blockIdx.z >> 3, sk = blockIdx.z & 7;
    int kbeg = sk * KSPLIT;
    int tid = threadIdx.x, warp = tid >> 5, lane = tid & 31;
    int wm = (warp & 1) * 32, wn = (warp >> 1) * 32;

    const __nv_bfloat16* gA1 = g_om + (size_t)b*QP*NP;
    const __nv_bfloat16* gA2 = g_s  + (size_t)b*QP*NP;
    const __nv_bfloat16* gB  = g_tm + (size_t)b*QP*NP;

    int lrow = tid >> 2, lcol = (tid & 3) * 8;

    auto load_stage = [&](int buf, int k0) {
        #pragma unroll
        for (int it = 0; it < 2; it++) {
            int row = lrow + it*32;
            uint32_t d1 = smem_u32(&sbuf[buf][0][row*TPAD + lcol]);
            uint32_t d2 = smem_u32(&sbuf[buf][1][row*TPAD + lcol]);
            uint32_t d3 = smem_u32(&sbuf[buf][2][row*TPAD + lcol]);
            cpasync16(d1, gA1 + (size_t)(m0 + row)*NP + k0 + lcol);
            cpasync16(d2, gA2 + (size_t)(m0 + row)*NP + k0 + lcol);
            cpasync16(d3, gB  + (size_t)(n0 + row)*NP + k0 + lcol);
        }
    };

    float d1[2][4][4], d2[2][4][4];
    #pragma unroll
    for (int mi = 0; mi < 2; mi++)
        #pragma unroll
        for (int nj = 0; nj < 4; nj++)
            #pragma unroll
            for (int e = 0; e < 4; e++) { d1[mi][nj][e] = 0.f; d2[mi][nj][e] = 0.f; }

    int a_r = lane & 15, a_c = ((lane >> 4) & 1) * 8;
    int b_r = (lane & 7) + (((lane & 16) ? 8 : 0)), b_c = ((lane & 8) ? 8 : 0);

    load_stage(0, kbeg);            cp_commit();
    load_stage(1, kbeg + KSTAGE);   cp_commit();

    for (int s = 0; s < NSTAGES; s++) {
        if (s + 1 < NSTAGES) cp_wait<1>(); else cp_wait<0>();
        __syncthreads();
        if (s + 2 < NSTAGES) {
            load_stage((s + 2) % 3, kbeg + (s + 2)*KSTAGE);
            cp_commit();
        }

        int cur = s % 3;
        const __nv_bfloat16* t1 = sbuf[cur][0];
        const __nv_bfloat16* t2 = sbuf[cur][1];
        const __nv_bfloat16* tB = sbuf[cur][2];
        #pragma unroll
        for (int kk = 0; kk < 2; kk++) {
            uint32_t ao[2][4], as_[2][4], bf[2][4];
            #pragma unroll
            for (int mi = 0; mi < 2; mi++) {
                uint32_t off = (uint32_t)((wm + mi*16 + a_r)*TPAD + kk*16 + a_c)*2;
                ldsm4(ao[mi],  smem_u32(t1) + off);
                ldsm4(as_[mi], smem_u32(t2) + off);
            }
            #pragma unroll
            for (int nb = 0; nb < 2; nb++) {
                uint32_t off = (uint32_t)((wn + nb*16 + b_r)*TPAD + kk*16 + b_c)*2;
                ldsm4(bf[nb], smem_u32(tB) + off);
            }
            #pragma unroll
            for (int mi = 0; mi < 2; mi++)
                #pragma unroll
                for (int nj = 0; nj < 4; nj++) {
                    uint32_t b0 = bf[nj >> 1][(nj & 1)*2], b1 = bf[nj >> 1][(nj & 1)*2 + 1];
                    mma16816(d1[mi][nj], ao[mi],  b0, b1);
                    mma16816(d2[mi][nj], as_[mi], b0, b1);
                }
        }
    }

    float* C1 = g_C1p + (size_t)(sk*BB + b)*NQ*NT;
    float* C2 = g_C2p + (size_t)(sk*BB + b)*NQ*NT;
    int r = lane >> 2, c2 = (lane & 3)*2;
    #pragma unroll
    for (int mi = 0; mi < 2; mi++)
        #pragma unroll
        for (int nj = 0; nj < 4; nj++) {
            int m = m0 + wm + mi*16 + r;
            int n = n0 + wn + nj*8 + c2;
            if (m < NQ) {
                if (n     < NT) { C1[(size_t)m*NT + n]     = d1[mi][nj][0]; C2[(size_t)m*NT + n]     = d2[mi][nj][0]; }
                if (n + 1 < NT) { C1[(size_t)m*NT + n + 1] = d1[mi][nj][1]; C2[(size_t)m*NT + n + 1] = d2[mi][nj][1]; }
            }
            if (m + 8 < NQ) {
                if (n     < NT) { C1[(size_t)(m+8)*NT + n]     = d1[mi][nj][2]; C2[(size_t)(m+8)*NT + n]     = d2[mi][nj][2]; }
                if (n + 1 < NT) { C1[(size_t)(m+8)*NT + n + 1] = d1[mi][nj][3]; C2[(size_t)(m+8)*NT + n + 1] = d2[mi][nj][3]; }
            }
        }
}

// ---------------- K3: final cost --------------------------------------------
__global__ void k_final(const float* __restrict__ pb, const float* __restrict__ tb,
                        float* __restrict__ out) {
    int idx = blockIdx.x * 256 + threadIdx.x;
    if (idx >= BB*NQ*NT) return;
    int t = idx % NT; int r = idx / NT; int q = r % NQ; int b = r / NQ;

    float c1 = 0.f, c2 = 0.f;
    #pragma unroll
    for (int sk = 0; sk < SPLITK; sk++) {
        size_t off = ((size_t)(sk*BB + b)*NQ + q)*NT + t;
        c1 += g_C1p[off]; c2 += g_C2p[off];
    }
    float neg = g_negP[b*NQ + q] + g_negP[BB*NQ + b*NQ + q];
    float ss  = g_sP  [b*NQ + q] + g_sP  [BB*NQ + b*NQ + q];
    float ts  = g_tmsum[b*NT + t];
    float cost_mask = (neg - c1) * (1.0f/(float)NP);
    float cost_dice = 1.f - (2.f*c2 + 1.f) / (ss + ts + 1.f);

    float4 pbox = ((const float4*)pb)[(size_t)b*NQ + q];
    float4 tbox = ((const float4*)tb)[(size_t)b*NT + t];
    float l1 = fabsf(pbox.x - tbox.x) + fabsf(pbox.y - tbox.y)
             + fabsf(pbox.z - tbox.z) + fabsf(pbox.w - tbox.w);

    float ax0 = pbox.x - 0.5f*pbox.z, ay0 = pbox.y - 0.5f*pbox.w;
    float ax1 = pbox.x + 0.5f*pbox.z, ay1 = pbox.y + 0.5f*pbox.w;
    float bx0 = tbox.x - 0.5f*tbox.z, by0 = tbox.y - 0.5f*tbox.w;
    float bx1 = tbox.x + 0.5f*tbox.z, by1 = tbox.y + 0.5f*tbox.w;
    float areaA = (ax1 - ax0)*(ay1 - ay0);
    float areaB = (bx1 - bx0)*(by1 - by0);
    float iw = fmaxf(fminf(ax1, bx1) - fmaxf(ax0, bx0), 0.f);
    float ih = fmaxf(fminf(ay1, by1) - fmaxf(ay0, by0), 0.f);
    float inter = iw * ih;
    float uni = areaA + areaB - inter;
    float iou = inter / uni;
    float ew = fmaxf(fmaxf(ax1, bx1) - fminf(ax0, bx0), 0.f);
    float eh = fmaxf(fmaxf(ay1, by1) - fminf(ay0, by0), 0.f);
    float areaE = ew * eh;
    float giou = iou - (areaE - uni) / areaE;

    out[idx] = 5.f*cost_mask + 5.f*cost_dice + 5.f*l1 - 2.f*giou;
}

// ---------------- launch ------------------------------------------------------
extern "C" void kernel_launch(void* const* d_in, const int* in_sizes, int n_in,
                              void* d_out, int out_size) {
    const float* pred_masks = (const float*)d_in[0];
    const float* tgt_masks  = (const float*)d_in[1];
    const float* pred_boxes = (const float*)d_in[2];
    const float* tgt_boxes  = (const float*)d_in[3];
    const float* pts        = (const float*)d_in[4];
    float* out = (float*)d_out;

    static cudaStream_t side = []() {
        cudaStream_t s; cudaStreamCreateWithFlags(&s, cudaStreamNonBlocking); return s;
    }();
    static cudaEvent_t evFork = []() { cudaEvent_t e; cudaEventCreateWithFlags(&e, cudaEventDisableTiming); return e; }();
    static cudaEvent_t evJoin = []() { cudaEvent_t e; cudaEventCreateWithFlags(&e, cudaEventDisableTiming); return e; }();
    static bool attr_done = []() {
        cudaFuncSetAttribute(k_sample_pred, cudaFuncAttributeMaxDynamicSharedMemorySize,
                             PRED_MASK_BYTES + 64*4);
        return true;
    }();
    (void)attr_done;

    const int smem_pred = PRED_MASK_BYTES + 64*4;

    k_build<<<BB, 1024>>>(pts);
    cudaEventRecord(evFork, 0);
    cudaStreamWaitEvent(side, evFork, 0);

    k_sample_tgt <<<dim3(NT, BB), 512, 0, side>>>(tgt_masks);
    k_sample_pred<<<dim3(NQ, BB, 2), 1024, smem_pred>>>(pred_masks);
    cudaEventRecord(evJoin, side);
    cudaStreamWaitEvent(0, evJoin, 0);

    k_gemm<<<dim3(5, 5, BB*SPLITK), 128>>>();
    k_final<<<(BB*NQ*NT + 255)/256, 256>>>(pred_boxes, tgt_boxes, out);
}